// round 2
// baseline (speedup 1.0000x reference)
#include <cuda_runtime.h>
#include <math.h>

// Problem constants (fixed by the dataset)
#define B_   4
#define S_   512
#define N_   8
#define D_   256
#define H_   8
#define HD_  32
#define BN_  (B_ * N_)          // 32
#define T_   (BN_ * S_)         // 16384 rows
#define QKVN 768                // 3*D

// ---------------- scratch (device globals; no runtime allocation) -------------
__device__ float g_pe[S_ * D_];                 // 0.5 MB
__device__ float g_xr[(long)T_ * D_];           // 16 MB  (BN,S,D) with PE added
__device__ float g_wcat[QKVN * D_];             // 0.75 MB  rows: [Wq; Wk; Wv]
__device__ float g_bcat[QKVN];
__device__ float g_qkv[(long)T_ * QKVN];        // 48 MB  (t, 768)
__device__ float g_att[(long)T_ * D_];          // 16 MB  attention output (t, d)

// ---------------- 1) positional encoding table -------------------------------
__global__ void pe_kernel() {
    int idx = blockIdx.x * 256 + threadIdx.x;       // 65536 = S * D/2
    int s = idx >> 7;
    int i = idx & 127;
    float div = expf((float)(2 * i) * (-0.035977892078031970f)); // -ln(10000)/256
    float sn, cs;
    sincosf((float)s * div, &sn, &cs);
    g_pe[s * D_ + 2 * i]     = sn;
    g_pe[s * D_ + 2 * i + 1] = cs;
}

// ---------------- 2) x + pe, rearrange (B,S,N,D) -> (BN,S,D) -----------------
__global__ void addpe_kernel(const float* __restrict__ x) {
    int idx = blockIdx.x * 256 + threadIdx.x;       // 1,048,576 float4s
    int d4 = idx & 63;
    int s  = (idx >> 6) & 511;
    int bn = idx >> 15;                              // 512*64 = 2^15
    int b = bn >> 3, n = bn & 7;
    const float4 xv = *(const float4*)(x + ((((long)b * S_ + s) * N_ + n) * D_ + d4 * 4));
    const float4 pv = *(const float4*)(g_pe + (s * D_ + d4 * 4));
    float4 o;
    o.x = xv.x + pv.x; o.y = xv.y + pv.y; o.z = xv.z + pv.z; o.w = xv.w + pv.w;
    *(float4*)(g_xr + (long)idx * 4) = o;
}

// ---------------- 3) concat weights/biases -----------------------------------
__global__ void wcat_kernel(const float* __restrict__ Wq, const float* __restrict__ bq,
                            const float* __restrict__ Wk, const float* __restrict__ bk,
                            const float* __restrict__ Wv, const float* __restrict__ bv) {
    int idx = blockIdx.x * 256 + threadIdx.x;       // 196608
    int j = idx >> 8, k = idx & 255;
    const float* src; const float* bsrc;
    int jj = j & 255;
    if (j < 256)      { src = Wq; bsrc = bq; }
    else if (j < 512) { src = Wk; bsrc = bk; }
    else              { src = Wv; bsrc = bv; }
    g_wcat[idx] = src[jj * D_ + k];
    if (k == 0) g_bcat[j] = bsrc[jj];
}

// ---------------- 4) QKV GEMM: C[16384,768] = Xr @ Wcat^T + bcat --------------
// NT gemm. BM=128 BN=64 BK=16, 256 thr.
__global__ void __launch_bounds__(256) qkv_gemm_kernel() {
    __shared__ float As[16][132];
    __shared__ float Bs[16][68];
    const int tid = threadIdx.x;
    const int tx = tid & 15;        // 0..15 -> 4 cols each
    const int ty = tid >> 4;        // 0..15 -> 8 rows each
    const int mBase = blockIdx.y * 128;
    const int nBase = blockIdx.x * 64;

    float acc[8][4];
    #pragma unroll
    for (int i = 0; i < 8; ++i)
        #pragma unroll
        for (int j = 0; j < 4; ++j) acc[i][j] = 0.f;

    for (int k0 = 0; k0 < D_; k0 += 16) {
        #pragma unroll
        for (int r = 0; r < 2; ++r) {               // A tile: 512 float4
            int f = tid + 256 * r;
            int row = f >> 2, c4 = f & 3;
            float4 v = *(const float4*)(g_xr + ((long)(mBase + row) * D_ + k0 + c4 * 4));
            As[c4 * 4 + 0][row] = v.x;
            As[c4 * 4 + 1][row] = v.y;
            As[c4 * 4 + 2][row] = v.z;
            As[c4 * 4 + 3][row] = v.w;
        }
        {                                            // B tile: 256 float4
            int row = tid >> 2, c4 = tid & 3;
            float4 v = *(const float4*)(g_wcat + ((nBase + row) * D_ + k0 + c4 * 4));
            Bs[c4 * 4 + 0][row] = v.x;
            Bs[c4 * 4 + 1][row] = v.y;
            Bs[c4 * 4 + 2][row] = v.z;
            Bs[c4 * 4 + 3][row] = v.w;
        }
        __syncthreads();
        #pragma unroll
        for (int kk = 0; kk < 16; ++kk) {
            float a[8], b[4];
            *(float4*)&a[0] = *(const float4*)&As[kk][ty * 8];
            *(float4*)&a[4] = *(const float4*)&As[kk][ty * 8 + 4];
            *(float4*)&b[0] = *(const float4*)&Bs[kk][tx * 4];
            #pragma unroll
            for (int i = 0; i < 8; ++i)
                #pragma unroll
                for (int j = 0; j < 4; ++j)
                    acc[i][j] = fmaf(a[i], b[j], acc[i][j]);
        }
        __syncthreads();
    }

    const int jg = nBase + tx * 4;
    const float4 bia = *(const float4*)(g_bcat + jg);
    #pragma unroll
    for (int i = 0; i < 8; ++i) {
        int t = mBase + ty * 8 + i;
        float4 o;
        o.x = acc[i][0] + bia.x;
        o.y = acc[i][1] + bia.y;
        o.z = acc[i][2] + bia.z;
        o.w = acc[i][3] + bia.w;
        *(float4*)(g_qkv + ((long)t * QKVN + jg)) = o;
    }
}

// ---------------- 5) causal flash attention -----------------------------------
__global__ void __launch_bounds__(128) attn_kernel() {
    __shared__ float Ks[128][32];
    __shared__ float Vs[128][32];
    const int qc = blockIdx.x, h = blockIdx.y, bn = blockIdx.z;
    const int tid = threadIdx.x;
    const int q = qc * 128 + tid;
    const float scale = 0.17677669529663687f;   // 1/sqrt(32)

    float qreg[32];
    {
        const float* qptr = g_qkv + ((long)(bn * S_ + q) * QKVN + h * HD_);
        #pragma unroll
        for (int e4 = 0; e4 < 8; ++e4)
            *(float4*)&qreg[e4 * 4] = *(const float4*)(qptr + e4 * 4);
        #pragma unroll
        for (int e = 0; e < 32; ++e) qreg[e] *= scale;
    }

    float m = -1e30f, l = 0.f;
    float acc[32];
    #pragma unroll
    for (int e = 0; e < 32; ++e) acc[e] = 0.f;

    const int nchunks = qc + 1;
    for (int c = 0; c < nchunks; ++c) {
        #pragma unroll
        for (int r = 0; r < 8; ++r) {
            int f = tid + 128 * r;
            int row = f >> 3, e4 = f & 7;
            const float* base = g_qkv + ((long)(bn * S_ + c * 128 + row) * QKVN + D_ + h * HD_ + e4 * 4);
            *(float4*)&Ks[row][e4 * 4] = *(const float4*)base;
            *(float4*)&Vs[row][e4 * 4] = *(const float4*)(base + D_);
        }
        __syncthreads();

        const int kmax = min(128, q - c * 128 + 1);
        for (int k = 0; k < kmax; ++k) {
            const float4* krow = (const float4*)Ks[k];
            float s0 = 0.f, s1 = 0.f, s2 = 0.f, s3 = 0.f;
            #pragma unroll
            for (int e4 = 0; e4 < 8; ++e4) {
                float4 kv = krow[e4];
                s0 = fmaf(qreg[e4 * 4 + 0], kv.x, s0);
                s1 = fmaf(qreg[e4 * 4 + 1], kv.y, s1);
                s2 = fmaf(qreg[e4 * 4 + 2], kv.z, s2);
                s3 = fmaf(qreg[e4 * 4 + 3], kv.w, s3);
            }
            float s = (s0 + s1) + (s2 + s3);
            float mn = fmaxf(m, s);
            float p = __expf(s - mn);
            if (mn > m) {
                float corr = __expf(m - mn);
                l *= corr;
                #pragma unroll
                for (int e = 0; e < 32; ++e) acc[e] *= corr;
                m = mn;
            }
            l += p;
            const float4* vrow = (const float4*)Vs[k];
            #pragma unroll
            for (int e4 = 0; e4 < 8; ++e4) {
                float4 vv = vrow[e4];
                acc[e4 * 4 + 0] = fmaf(p, vv.x, acc[e4 * 4 + 0]);
                acc[e4 * 4 + 1] = fmaf(p, vv.y, acc[e4 * 4 + 1]);
                acc[e4 * 4 + 2] = fmaf(p, vv.z, acc[e4 * 4 + 2]);
                acc[e4 * 4 + 3] = fmaf(p, vv.w, acc[e4 * 4 + 3]);
            }
        }
        __syncthreads();
    }

    const float inv = 1.f / l;
    float* optr = g_att + ((long)(bn * S_ + q) * D_ + h * HD_);
    #pragma unroll
    for (int e4 = 0; e4 < 8; ++e4) {
        float4 o;
        o.x = acc[e4 * 4 + 0] * inv;
        o.y = acc[e4 * 4 + 1] * inv;
        o.z = acc[e4 * 4 + 2] * inv;
        o.w = acc[e4 * 4 + 3] * inv;
        *(float4*)(optr + e4 * 4) = o;
    }
}

// ---------------- 6) out-proj GEMM + residual + LayerNorm ---------------------
__global__ void __launch_bounds__(256) oproj_ln_kernel(
    const float* __restrict__ Wo, const float* __restrict__ bo,
    const float* __restrict__ x,  const float* __restrict__ gamma,
    const float* __restrict__ beta, float* __restrict__ out)
{
    __shared__ float As[16][36];     // [k][m]
    __shared__ float Bs[16][260];    // [k][n]
    const int tx = threadIdx.x;      // 0..31 (lane)
    const int ty = threadIdx.y;      // 0..7
    const int tid = ty * 32 + tx;
    const int mBase = blockIdx.x * 32;

    float acc[4][8];
    #pragma unroll
    for (int i = 0; i < 4; ++i)
        #pragma unroll
        for (int j = 0; j < 8; ++j) acc[i][j] = 0.f;

    for (int k0 = 0; k0 < D_; k0 += 16) {
        if (tid < 128) {                             // A tile: 128 float4
            int row = tid >> 2, c4 = tid & 3;
            float4 v = *(const float4*)(g_att + ((long)(mBase + row) * D_ + k0 + c4 * 4));
            As[c4 * 4 + 0][row] = v.x;
            As[c4 * 4 + 1][row] = v.y;
            As[c4 * 4 + 2][row] = v.z;
            As[c4 * 4 + 3][row] = v.w;
        }
        #pragma unroll
        for (int r = 0; r < 4; ++r) {                // B tile: 1024 float4
            int f = tid + 256 * r;
            int row = f >> 2, c4 = f & 3;
            float4 v = *(const float4*)(Wo + (row * D_ + k0 + c4 * 4));
            Bs[c4 * 4 + 0][row] = v.x;
            Bs[c4 * 4 + 1][row] = v.y;
            Bs[c4 * 4 + 2][row] = v.z;
            Bs[c4 * 4 + 3][row] = v.w;
        }
        __syncthreads();
        #pragma unroll
        for (int kk = 0; kk < 16; ++kk) {
            float a[4], b[8];
            *(float4*)&a[0] = *(const float4*)&As[kk][ty * 4];
            *(float4*)&b[0] = *(const float4*)&Bs[kk][tx * 8];
            *(float4*)&b[4] = *(const float4*)&Bs[kk][tx * 8 + 4];
            #pragma unroll
            for (int i = 0; i < 4; ++i)
                #pragma unroll
                for (int j = 0; j < 8; ++j)
                    acc[i][j] = fmaf(a[i], b[j], acc[i][j]);
        }
        __syncthreads();
    }

    float g[8], bt[8], bia[8];
    *(float4*)&g[0]  = *(const float4*)(gamma + tx * 8);
    *(float4*)&g[4]  = *(const float4*)(gamma + tx * 8 + 4);
    *(float4*)&bt[0] = *(const float4*)(beta  + tx * 8);
    *(float4*)&bt[4] = *(const float4*)(beta  + tx * 8 + 4);
    *(float4*)&bia[0] = *(const float4*)(bo + tx * 8);
    *(float4*)&bia[4] = *(const float4*)(bo + tx * 8 + 4);

    #pragma unroll
    for (int i = 0; i < 4; ++i) {
        int t = mBase + ty * 4 + i;
        int bn = t >> 9, s = t & 511;
        int b = bn >> 3, n = bn & 7;
        const float* xrow = x + (((long)(b * S_ + s) * N_ + n) * D_);
        float v[8];
        float xv[8];
        *(float4*)&xv[0] = *(const float4*)(xrow + tx * 8);
        *(float4*)&xv[4] = *(const float4*)(xrow + tx * 8 + 4);
        float sum = 0.f, sq = 0.f;
        #pragma unroll
        for (int j = 0; j < 8; ++j) {
            v[j] = acc[i][j] + bia[j] + xv[j];
            sum += v[j];
            sq  = fmaf(v[j], v[j], sq);
        }
        #pragma unroll
        for (int o = 16; o > 0; o >>= 1) {
            sum += __shfl_xor_sync(0xFFFFFFFFu, sum, o);
            sq  += __shfl_xor_sync(0xFFFFFFFFu, sq,  o);
        }
        float mu   = sum * (1.f / 256.f);
        float var  = sq * (1.f / 256.f) - mu * mu;
        float rstd = rsqrtf(var + 1e-5f);
        float* orow = out + (((long)(b * S_ + s) * N_ + n) * D_);
        float4 o1, o2;
        o1.x = (v[0] - mu) * rstd * g[0] + bt[0];
        o1.y = (v[1] - mu) * rstd * g[1] + bt[1];
        o1.z = (v[2] - mu) * rstd * g[2] + bt[2];
        o1.w = (v[3] - mu) * rstd * g[3] + bt[3];
        o2.x = (v[4] - mu) * rstd * g[4] + bt[4];
        o2.y = (v[5] - mu) * rstd * g[5] + bt[5];
        o2.z = (v[6] - mu) * rstd * g[6] + bt[6];
        o2.w = (v[7] - mu) * rstd * g[7] + bt[7];
        *(float4*)(orow + tx * 8)     = o1;
        *(float4*)(orow + tx * 8 + 4) = o2;
    }
}

// ------------------------------ launch ----------------------------------------
// Input order per metadata (dict insertion order in setup_inputs):
//   0:x 1:Wq 2:Wk 3:Wv 4:Wo 5:bq 6:bk 7:bv 8:bo 9:gamma 10:beta 11:num_heads
extern "C" void kernel_launch(void* const* d_in, const int* in_sizes, int n_in,
                              void* d_out, int out_size) {
    const float* x     = (const float*)d_in[0];
    const float* Wq    = (const float*)d_in[1];
    const float* Wk    = (const float*)d_in[2];
    const float* Wv    = (const float*)d_in[3];
    const float* Wo    = (const float*)d_in[4];
    const float* bq    = (const float*)d_in[5];
    const float* bk    = (const float*)d_in[6];
    const float* bv    = (const float*)d_in[7];
    const float* bo    = (const float*)d_in[8];
    const float* gamma = (const float*)d_in[9];
    const float* beta  = (const float*)d_in[10];
    float* out = (float*)d_out;

    pe_kernel<<<256, 256>>>();
    addpe_kernel<<<4096, 256>>>(x);
    wcat_kernel<<<768, 256>>>(Wq, bq, Wk, bk, Wv, bv);
    qkv_gemm_kernel<<<dim3(12, 128), 256>>>();
    attn_kernel<<<dim3(4, H_, BN_), 128>>>();
    oproj_ln_kernel<<<512, dim3(32, 8)>>>(Wo, bo, x, gamma, beta, out);
}

// round 3
// speedup vs baseline: 1.0799x; 1.0799x over previous
#include <cuda_runtime.h>
#include <math.h>

// Problem constants (fixed by the dataset)
#define B_   4
#define S_   512
#define N_   8
#define D_   256
#define H_   8
#define HD_  32
#define BN_  (B_ * N_)          // 32
#define T_   (BN_ * S_)         // 16384 rows
#define QKVN 768                // 3*D

typedef unsigned long long u64;

// ---------------- f32x2 packed-math helpers (sm_103a FFMA2) -------------------
__device__ __forceinline__ u64 pack2(float lo, float hi) {
    u64 r; asm("mov.b64 %0, {%1, %2};" : "=l"(r) : "f"(lo), "f"(hi)); return r;
}
__device__ __forceinline__ void unpack2(u64 v, float& lo, float& hi) {
    asm("mov.b64 {%0, %1}, %2;" : "=f"(lo), "=f"(hi) : "l"(v));
}
__device__ __forceinline__ u64 fma2(u64 a, u64 b, u64 c) {
    u64 d; asm("fma.rn.f32x2 %0, %1, %2, %3;" : "=l"(d) : "l"(a), "l"(b), "l"(c)); return d;
}
__device__ __forceinline__ u64 mul2(u64 a, u64 b) {
    u64 d; asm("mul.rn.f32x2 %0, %1, %2;" : "=l"(d) : "l"(a), "l"(b)); return d;
}
__device__ __forceinline__ u64 add2(u64 a, u64 b) {
    u64 d; asm("add.rn.f32x2 %0, %1, %2;" : "=l"(d) : "l"(a), "l"(b)); return d;
}

// ---------------- scratch (device globals; no runtime allocation) -------------
__device__ float g_pe[S_ * D_];
__device__ float g_xr[(long)T_ * D_];
__device__ float g_wcat[QKVN * D_];
__device__ float g_bcat[QKVN];
__device__ float g_qkv[(long)T_ * QKVN];
__device__ float g_att[(long)T_ * D_];

// ---------------- 1) positional encoding table -------------------------------
__global__ void pe_kernel() {
    int idx = blockIdx.x * 256 + threadIdx.x;       // 65536 = S * D/2
    int s = idx >> 7;
    int i = idx & 127;
    float div = expf((float)(2 * i) * (-0.035977892078031970f)); // -ln(10000)/256
    float sn, cs;
    sincosf((float)s * div, &sn, &cs);
    g_pe[s * D_ + 2 * i]     = sn;
    g_pe[s * D_ + 2 * i + 1] = cs;
}

// ---------------- 2) x + pe, rearrange (B,S,N,D) -> (BN,S,D) -----------------
__global__ void addpe_kernel(const float* __restrict__ x) {
    int idx = blockIdx.x * 256 + threadIdx.x;       // 1,048,576 float4s
    int d4 = idx & 63;
    int s  = (idx >> 6) & 511;
    int bn = idx >> 15;
    int b = bn >> 3, n = bn & 7;
    const float4 xv = *(const float4*)(x + ((((long)b * S_ + s) * N_ + n) * D_ + d4 * 4));
    const float4 pv = *(const float4*)(g_pe + (s * D_ + d4 * 4));
    float4 o;
    o.x = xv.x + pv.x; o.y = xv.y + pv.y; o.z = xv.z + pv.z; o.w = xv.w + pv.w;
    *(float4*)(g_xr + (long)idx * 4) = o;
}

// ---------------- 3) concat weights/biases -----------------------------------
__global__ void wcat_kernel(const float* __restrict__ Wq, const float* __restrict__ bq,
                            const float* __restrict__ Wk, const float* __restrict__ bk,
                            const float* __restrict__ Wv, const float* __restrict__ bv) {
    int idx = blockIdx.x * 256 + threadIdx.x;       // 196608
    int j = idx >> 8, k = idx & 255;
    const float* src; const float* bsrc;
    int jj = j & 255;
    if (j < 256)      { src = Wq; bsrc = bq; }
    else if (j < 512) { src = Wk; bsrc = bk; }
    else              { src = Wv; bsrc = bv; }
    g_wcat[idx] = src[jj * D_ + k];
    if (k == 0) g_bcat[j] = bsrc[jj];
}

// ---------------- 4) QKV GEMM: C[16384,768] = Xr @ Wcat^T + bcat --------------
// NT gemm. BM=128 BN=128 BK=16, 256 thr (16x16), per-thread 8x8, f32x2 m-packed.
__global__ void __launch_bounds__(256) qkv_gemm_kernel() {
    __shared__ float As[16][132];   // [k][m], 132 floats = 528B = 33*16B (16B-aligned rows)
    __shared__ float Bs[16][132];   // [k][n]
    const int tid = threadIdx.x;
    const int tx = tid & 15;        // n: 8 cols each
    const int ty = tid >> 4;        // m: 8 rows each
    const int mBase = blockIdx.y * 128;
    const int nBase = blockIdx.x * 128;

    u64 acc[4][8];                  // [m-pair][n]
    #pragma unroll
    for (int i = 0; i < 4; ++i)
        #pragma unroll
        for (int j = 0; j < 8; ++j) acc[i][j] = 0ULL;

    for (int k0 = 0; k0 < D_; k0 += 16) {
        #pragma unroll
        for (int r = 0; r < 2; ++r) {               // A tile: 512 float4
            int f = tid + 256 * r;
            int row = f >> 2, c4 = f & 3;
            float4 v = *(const float4*)(g_xr + ((long)(mBase + row) * D_ + k0 + c4 * 4));
            As[c4 * 4 + 0][row] = v.x;
            As[c4 * 4 + 1][row] = v.y;
            As[c4 * 4 + 2][row] = v.z;
            As[c4 * 4 + 3][row] = v.w;
        }
        #pragma unroll
        for (int r = 0; r < 2; ++r) {               // B tile: 512 float4
            int f = tid + 256 * r;
            int row = f >> 2, c4 = f & 3;
            float4 v = *(const float4*)(g_wcat + ((nBase + row) * D_ + k0 + c4 * 4));
            Bs[c4 * 4 + 0][row] = v.x;
            Bs[c4 * 4 + 1][row] = v.y;
            Bs[c4 * 4 + 2][row] = v.z;
            Bs[c4 * 4 + 3][row] = v.w;
        }
        __syncthreads();
        #pragma unroll
        for (int kk = 0; kk < 16; ++kk) {
            // a: 8 m-values as 4 packed pairs (natural pairing, contiguous m)
            const ulonglong2* ap = (const ulonglong2*)&As[kk][ty * 8];
            ulonglong2 av0 = ap[0], av1 = ap[1];
            u64 a2[4] = {av0.x, av0.y, av1.x, av1.y};
            // b: 8 n-values, each duplicated into both halves
            float4 b0 = *(const float4*)&Bs[kk][tx * 8];
            float4 b1 = *(const float4*)&Bs[kk][tx * 8 + 4];
            u64 bb[8];
            bb[0] = pack2(b0.x, b0.x); bb[1] = pack2(b0.y, b0.y);
            bb[2] = pack2(b0.z, b0.z); bb[3] = pack2(b0.w, b0.w);
            bb[4] = pack2(b1.x, b1.x); bb[5] = pack2(b1.y, b1.y);
            bb[6] = pack2(b1.z, b1.z); bb[7] = pack2(b1.w, b1.w);
            #pragma unroll
            for (int mi = 0; mi < 4; ++mi)
                #pragma unroll
                for (int nj = 0; nj < 8; ++nj)
                    acc[mi][nj] = fma2(a2[mi], bb[nj], acc[mi][nj]);
        }
        __syncthreads();
    }

    // epilogue: add bias, unpack, store two rows per m-pair
    const int jg = nBase + tx * 8;
    float bias[8];
    *(float4*)&bias[0] = *(const float4*)(g_bcat + jg);
    *(float4*)&bias[4] = *(const float4*)(g_bcat + jg + 4);
    #pragma unroll
    for (int mi = 0; mi < 4; ++mi) {
        int t0 = mBase + ty * 8 + 2 * mi;
        float r0[8], r1[8];
        #pragma unroll
        for (int nj = 0; nj < 8; ++nj) {
            float lo, hi;
            unpack2(acc[mi][nj], lo, hi);
            r0[nj] = lo + bias[nj];
            r1[nj] = hi + bias[nj];
        }
        float* p0 = g_qkv + ((long)t0 * QKVN + jg);
        float* p1 = p0 + QKVN;
        *(float4*)p0       = *(float4*)&r0[0];
        *(float4*)(p0 + 4) = *(float4*)&r0[4];
        *(float4*)p1       = *(float4*)&r1[0];
        *(float4*)(p1 + 4) = *(float4*)&r1[4];
    }
}

// ---------------- 5) causal flash attention (f32x2) ---------------------------
__global__ void __launch_bounds__(128) attn_kernel() {
    __shared__ float Ks[128][32];
    __shared__ float Vs[128][32];
    const int qc = blockIdx.x, h = blockIdx.y, bn = blockIdx.z;
    const int tid = threadIdx.x;
    const int q = qc * 128 + tid;
    const float scale = 0.17677669529663687f;   // 1/sqrt(32)

    u64 qreg[16];
    {
        const float* qptr = g_qkv + ((long)(bn * S_ + q) * QKVN + h * HD_);
        const u64 sc2 = pack2(scale, scale);
        #pragma unroll
        for (int e = 0; e < 16; ++e)
            qreg[e] = mul2(((const u64*)qptr)[e], sc2);
    }

    float m = -1e30f, l = 0.f;
    u64 acc[16];
    #pragma unroll
    for (int e = 0; e < 16; ++e) acc[e] = 0ULL;

    const int nchunks = qc + 1;
    for (int c = 0; c < nchunks; ++c) {
        #pragma unroll
        for (int r = 0; r < 8; ++r) {
            int f = tid + 128 * r;
            int row = f >> 3, e4 = f & 7;
            const float* base = g_qkv + ((long)(bn * S_ + c * 128 + row) * QKVN + D_ + h * HD_ + e4 * 4);
            *(float4*)&Ks[row][e4 * 4] = *(const float4*)base;
            *(float4*)&Vs[row][e4 * 4] = *(const float4*)(base + D_);
        }
        __syncthreads();

        const int kmax = min(128, q - c * 128 + 1);
        for (int k = 0; k < kmax; ++k) {
            const u64* krow = (const u64*)Ks[k];
            u64 s2[4];
            #pragma unroll
            for (int e = 0; e < 4; ++e) s2[e] = mul2(qreg[e], krow[e]);
            #pragma unroll
            for (int e = 4; e < 16; ++e) s2[e & 3] = fma2(qreg[e], krow[e], s2[e & 3]);
            s2[0] = add2(s2[0], s2[1]);
            s2[2] = add2(s2[2], s2[3]);
            s2[0] = add2(s2[0], s2[2]);
            float slo, shi;
            unpack2(s2[0], slo, shi);
            float s = slo + shi;

            float mn = fmaxf(m, s);
            float p = __expf(s - mn);
            if (mn > m) {
                float corr = __expf(m - mn);
                l *= corr;
                const u64 c2 = pack2(corr, corr);
                #pragma unroll
                for (int e = 0; e < 16; ++e) acc[e] = mul2(acc[e], c2);
                m = mn;
            }
            l += p;
            const u64 p2 = pack2(p, p);
            const u64* vrow = (const u64*)Vs[k];
            #pragma unroll
            for (int e = 0; e < 16; ++e)
                acc[e] = fma2(p2, vrow[e], acc[e]);
        }
        __syncthreads();
    }

    const float inv = 1.f / l;
    const u64 inv2 = pack2(inv, inv);
    u64* optr = (u64*)(g_att + ((long)(bn * S_ + q) * D_ + h * HD_));
    #pragma unroll
    for (int e = 0; e < 16; ++e)
        optr[e] = mul2(acc[e], inv2);
}

// ---------------- 6) out-proj GEMM + residual + LayerNorm (f32x2) -------------
__global__ void __launch_bounds__(256) oproj_ln_kernel(
    const float* __restrict__ Wo, const float* __restrict__ bo,
    const float* __restrict__ x,  const float* __restrict__ gamma,
    const float* __restrict__ beta, float* __restrict__ out)
{
    __shared__ float As[16][36];     // [k][m]
    __shared__ float Bs[16][260];    // [k][n] (260*4 = 1040 = 65*16, 16B-aligned rows)
    const int tx = threadIdx.x;      // 0..31 (lane)
    const int ty = threadIdx.y;      // 0..7
    const int tid = ty * 32 + tx;
    const int mBase = blockIdx.x * 32;

    u64 acc[4][4];                   // [m][n-pair]
    #pragma unroll
    for (int i = 0; i < 4; ++i)
        #pragma unroll
        for (int j = 0; j < 4; ++j) acc[i][j] = 0ULL;

    for (int k0 = 0; k0 < D_; k0 += 16) {
        if (tid < 128) {                             // A tile: 128 float4
            int row = tid >> 2, c4 = tid & 3;
            float4 v = *(const float4*)(g_att + ((long)(mBase + row) * D_ + k0 + c4 * 4));
            As[c4 * 4 + 0][row] = v.x;
            As[c4 * 4 + 1][row] = v.y;
            As[c4 * 4 + 2][row] = v.z;
            As[c4 * 4 + 3][row] = v.w;
        }
        #pragma unroll
        for (int r = 0; r < 4; ++r) {                // B tile: 1024 float4
            int f = tid + 256 * r;
            int row = f >> 2, c4 = f & 3;
            float4 v = *(const float4*)(Wo + (row * D_ + k0 + c4 * 4));
            Bs[c4 * 4 + 0][row] = v.x;
            Bs[c4 * 4 + 1][row] = v.y;
            Bs[c4 * 4 + 2][row] = v.z;
            Bs[c4 * 4 + 3][row] = v.w;
        }
        __syncthreads();
        #pragma unroll
        for (int kk = 0; kk < 16; ++kk) {
            float a[4];
            *(float4*)&a[0] = *(const float4*)&As[kk][ty * 4];
            const ulonglong2* bp = (const ulonglong2*)&Bs[kk][tx * 8];
            ulonglong2 bv0 = bp[0], bv1 = bp[1];
            u64 b2[4] = {bv0.x, bv0.y, bv1.x, bv1.y};
            u64 aa[4];
            aa[0] = pack2(a[0], a[0]); aa[1] = pack2(a[1], a[1]);
            aa[2] = pack2(a[2], a[2]); aa[3] = pack2(a[3], a[3]);
            #pragma unroll
            for (int i = 0; i < 4; ++i)
                #pragma unroll
                for (int j = 0; j < 4; ++j)
                    acc[i][j] = fma2(aa[i], b2[j], acc[i][j]);
        }
        __syncthreads();
    }

    float g[8], bt[8], bia[8];
    *(float4*)&g[0]  = *(const float4*)(gamma + tx * 8);
    *(float4*)&g[4]  = *(const float4*)(gamma + tx * 8 + 4);
    *(float4*)&bt[0] = *(const float4*)(beta  + tx * 8);
    *(float4*)&bt[4] = *(const float4*)(beta  + tx * 8 + 4);
    *(float4*)&bia[0] = *(const float4*)(bo + tx * 8);
    *(float4*)&bia[4] = *(const float4*)(bo + tx * 8 + 4);

    #pragma unroll
    for (int i = 0; i < 4; ++i) {
        int t = mBase + ty * 4 + i;
        int bn = t >> 9, s = t & 511;
        int b = bn >> 3, n = bn & 7;
        const float* xrow = x + (((long)(b * S_ + s) * N_ + n) * D_);
        float v[8];
        float xv[8];
        *(float4*)&xv[0] = *(const float4*)(xrow + tx * 8);
        *(float4*)&xv[4] = *(const float4*)(xrow + tx * 8 + 4);
        #pragma unroll
        for (int j = 0; j < 4; ++j)
            unpack2(acc[i][j], v[2 * j], v[2 * j + 1]);
        float sum = 0.f, sq = 0.f;
        #pragma unroll
        for (int j = 0; j < 8; ++j) {
            v[j] = v[j] + bia[j] + xv[j];
            sum += v[j];
            sq  = fmaf(v[j], v[j], sq);
        }
        #pragma unroll
        for (int o = 16; o > 0; o >>= 1) {
            sum += __shfl_xor_sync(0xFFFFFFFFu, sum, o);
            sq  += __shfl_xor_sync(0xFFFFFFFFu, sq,  o);
        }
        float mu   = sum * (1.f / 256.f);
        float var  = sq * (1.f / 256.f) - mu * mu;
        float rstd = rsqrtf(var + 1e-5f);
        float* orow = out + (((long)(b * S_ + s) * N_ + n) * D_);
        float4 o1, o2;
        o1.x = (v[0] - mu) * rstd * g[0] + bt[0];
        o1.y = (v[1] - mu) * rstd * g[1] + bt[1];
        o1.z = (v[2] - mu) * rstd * g[2] + bt[2];
        o1.w = (v[3] - mu) * rstd * g[3] + bt[3];
        o2.x = (v[4] - mu) * rstd * g[4] + bt[4];
        o2.y = (v[5] - mu) * rstd * g[5] + bt[5];
        o2.z = (v[6] - mu) * rstd * g[6] + bt[6];
        o2.w = (v[7] - mu) * rstd * g[7] + bt[7];
        *(float4*)(orow + tx * 8)     = o1;
        *(float4*)(orow + tx * 8 + 4) = o2;
    }
}

// ------------------------------ launch ----------------------------------------
// Input order per metadata (dict insertion order in setup_inputs):
//   0:x 1:Wq 2:Wk 3:Wv 4:Wo 5:bq 6:bk 7:bv 8:bo 9:gamma 10:beta 11:num_heads
extern "C" void kernel_launch(void* const* d_in, const int* in_sizes, int n_in,
                              void* d_out, int out_size) {
    const float* x     = (const float*)d_in[0];
    const float* Wq    = (const float*)d_in[1];
    const float* Wk    = (const float*)d_in[2];
    const float* Wv    = (const float*)d_in[3];
    const float* Wo    = (const float*)d_in[4];
    const float* bq    = (const float*)d_in[5];
    const float* bk    = (const float*)d_in[6];
    const float* bv    = (const float*)d_in[7];
    const float* bo    = (const float*)d_in[8];
    const float* gamma = (const float*)d_in[9];
    const float* beta  = (const float*)d_in[10];
    float* out = (float*)d_out;

    pe_kernel<<<256, 256>>>();
    addpe_kernel<<<4096, 256>>>(x);
    wcat_kernel<<<768, 256>>>(Wq, bq, Wk, bk, Wv, bv);
    qkv_gemm_kernel<<<dim3(6, 128), 256>>>();
    attn_kernel<<<dim3(4, H_, BN_), 128>>>();
    oproj_ln_kernel<<<512, dim3(32, 8)>>>(Wo, bo, x, gamma, beta, out);
}

// round 5
// speedup vs baseline: 1.5511x; 1.4364x over previous
#include <cuda_runtime.h>
#include <cuda_bf16.h>
#include <math.h>
#include <stdint.h>

// Problem constants (fixed by the dataset)
#define B_   4
#define S_   512
#define N_   8
#define D_   256
#define H_   8
#define HD_  32
#define BN_  (B_ * N_)          // 32
#define T_   (BN_ * S_)         // 16384 rows
#define QKVN 768                // 3*D

typedef unsigned long long u64;

// ---------------- f32x2 packed-math helpers (attention kernel) ----------------
__device__ __forceinline__ u64 pack2(float lo, float hi) {
    u64 r; asm("mov.b64 %0, {%1, %2};" : "=l"(r) : "f"(lo), "f"(hi)); return r;
}
__device__ __forceinline__ void unpack2(u64 v, float& lo, float& hi) {
    asm("mov.b64 {%0, %1}, %2;" : "=f"(lo), "=f"(hi) : "l"(v));
}
__device__ __forceinline__ u64 fma2(u64 a, u64 b, u64 c) {
    u64 d; asm("fma.rn.f32x2 %0, %1, %2, %3;" : "=l"(d) : "l"(a), "l"(b), "l"(c)); return d;
}
__device__ __forceinline__ u64 mul2(u64 a, u64 b) {
    u64 d; asm("mul.rn.f32x2 %0, %1, %2;" : "=l"(d) : "l"(a), "l"(b)); return d;
}
__device__ __forceinline__ u64 add2(u64 a, u64 b) {
    u64 d; asm("add.rn.f32x2 %0, %1, %2;" : "=l"(d) : "l"(a), "l"(b)); return d;
}

// ---------------- warp-mma helpers (baseline PTX, sm_80+) ---------------------
__device__ __forceinline__ uint32_t smem_u32(const void* p) {
    uint32_t a;
    asm("{ .reg .u64 t; cvta.to.shared.u64 t, %1; cvt.u32.u64 %0, t; }" : "=r"(a) : "l"(p));
    return a;
}
__device__ __forceinline__ void ldsm_x4(uint32_t& r0, uint32_t& r1, uint32_t& r2, uint32_t& r3,
                                        uint32_t addr) {
    asm volatile("ldmatrix.sync.aligned.m8n8.x4.shared.b16 {%0,%1,%2,%3}, [%4];"
        : "=r"(r0), "=r"(r1), "=r"(r2), "=r"(r3) : "r"(addr));
}
__device__ __forceinline__ void mma_bf16(float* c, const uint32_t* a, uint32_t b0, uint32_t b1) {
    asm volatile(
        "mma.sync.aligned.m16n8k16.row.col.f32.bf16.bf16.f32 "
        "{%0,%1,%2,%3}, {%4,%5,%6,%7}, {%8,%9}, {%0,%1,%2,%3};"
        : "+f"(c[0]), "+f"(c[1]), "+f"(c[2]), "+f"(c[3])
        : "r"(a[0]), "r"(a[1]), "r"(a[2]), "r"(a[3]), "r"(b0), "r"(b1));
}
#define SWZ128(off) ((off) ^ (((off) >> 3) & 0x70))

// ---------------- scratch (device globals; no runtime allocation) -------------
__device__ float g_pe[S_ * D_];                        // 0.5 MB
__device__ __nv_bfloat16 g_a2[(long)T_ * 512];         // 16 MB  [hi(256)|lo(256)] per row
__device__ __nv_bfloat16 g_w2[QKVN * 512];             // 0.75 MB [Whi|Wlo] rows q,k,v
__device__ __nv_bfloat16 g_wo2[D_ * 512];              // 0.25 MB
__device__ float g_bcat[QKVN];
__device__ float g_qkv[(long)T_ * QKVN];               // 48 MB fp32
__device__ __nv_bfloat16 g_att2[(long)T_ * 512];       // 16 MB attention out hi/lo
__device__ float g_y[(long)T_ * D_];                   // 16 MB out-proj result

// ---------------- 1) positional encoding table -------------------------------
__global__ void pe_kernel() {
    int idx = blockIdx.x * 256 + threadIdx.x;       // 65536 = S * D/2
    int s = idx >> 7;
    int i = idx & 127;
    float div = expf((float)(2 * i) * (-0.035977892078031970f)); // -ln(10000)/256
    float sn, cs;
    sincosf((float)s * div, &sn, &cs);
    g_pe[s * D_ + 2 * i]     = sn;
    g_pe[s * D_ + 2 * i + 1] = cs;
}

// ---------------- 2) x + pe -> bf16 hi/lo split, (B,S,N,D)->(BN,S,D) ----------
__global__ void addpe_split_kernel(const float* __restrict__ x) {
    int idx = blockIdx.x * 256 + threadIdx.x;       // 1,048,576 groups of 4
    int d4 = idx & 63;
    int s  = (idx >> 6) & 511;
    int bn = idx >> 15;
    int b = bn >> 3, n = bn & 7;
    const float4 xv = *(const float4*)(x + ((((long)b * S_ + s) * N_ + n) * D_ + d4 * 4));
    const float4 pv = *(const float4*)(g_pe + (s * D_ + d4 * 4));
    float v[4] = {xv.x + pv.x, xv.y + pv.y, xv.z + pv.z, xv.w + pv.w};
    __nv_bfloat16 hi[4]; float lo[4];
    #pragma unroll
    for (int j = 0; j < 4; ++j) {
        hi[j] = __float2bfloat16(v[j]);
        lo[j] = v[j] - __bfloat162float(hi[j]);
    }
    long t = (long)bn * S_ + s;
    __nv_bfloat16* hb = g_a2 + t * 512 + d4 * 4;
    __nv_bfloat162 h01; h01.x = hi[0]; h01.y = hi[1];
    __nv_bfloat162 h23; h23.x = hi[2]; h23.y = hi[3];
    ((__nv_bfloat162*)hb)[0] = h01;
    ((__nv_bfloat162*)hb)[1] = h23;
    __nv_bfloat162 l01; l01.x = __float2bfloat16(lo[0]); l01.y = __float2bfloat16(lo[1]);
    __nv_bfloat162 l23; l23.x = __float2bfloat16(lo[2]); l23.y = __float2bfloat16(lo[3]);
    ((__nv_bfloat162*)(hb + 256))[0] = l01;
    ((__nv_bfloat162*)(hb + 256))[1] = l23;
}

// ---------------- 3) weight concat + hi/lo split ------------------------------
__global__ void wsplit_kernel(const float* __restrict__ Wq, const float* __restrict__ bq,
                              const float* __restrict__ Wk, const float* __restrict__ bk,
                              const float* __restrict__ Wv, const float* __restrict__ bv) {
    int idx = blockIdx.x * 256 + threadIdx.x;       // 196608
    int j = idx >> 8, k = idx & 255;
    const float* src; const float* bsrc;
    int jj = j & 255;
    if (j < 256)      { src = Wq; bsrc = bq; }
    else if (j < 512) { src = Wk; bsrc = bk; }
    else              { src = Wv; bsrc = bv; }
    float v = src[jj * D_ + k];
    __nv_bfloat16 h = __float2bfloat16(v);
    g_w2[j * 512 + k]       = h;
    g_w2[j * 512 + 256 + k] = __float2bfloat16(v - __bfloat162float(h));
    if (k == 0) g_bcat[j] = bsrc[jj];
}

__global__ void wosplit_kernel(const float* __restrict__ Wo) {
    int idx = blockIdx.x * 256 + threadIdx.x;       // 65536
    int j = idx >> 8, k = idx & 255;
    float v = Wo[j * D_ + k];
    __nv_bfloat16 h = __float2bfloat16(v);
    g_wo2[j * 512 + k]       = h;
    g_wo2[j * 512 + 256 + k] = __float2bfloat16(v - __bfloat162float(h));
}

// ---------------- 4) warp-mma GEMM (3-term bf16 split) ------------------------
// C[M,N] (fp32) = A(hi+lo) @ W(hi+lo)^T as K'=768 bf16 GEMM, fp32 accum.
// Block tile 128x128, 8 warps (4x2), warp tile 32x64, K_tile=64, SW128 smem.
// which=0: qkv (A=g_a2, W=g_w2, C=g_qkv + bias, ldc=768)
// which=1: oproj (A=g_att2, W=g_wo2, C=g_y, ldc=256)
__global__ void __launch_bounds__(256) mma_gemm_kernel(int which) {
    __shared__ __align__(1024) __nv_bfloat16 As[128 * 64];  // 16 KB
    __shared__ __align__(1024) __nv_bfloat16 Ws[128 * 64];  // 16 KB
    const int tid = threadIdx.x;
    const int wid = tid >> 5, lane = tid & 31;
    const int wm = wid & 3;          // 4 warps along M (32 rows each)
    const int wn = wid >> 2;         // 2 warps along N (64 cols each)
    const int mBase = blockIdx.y * 128;
    const int nBase = blockIdx.x * 128;

    const __nv_bfloat16* __restrict__ Ag = which ? g_att2 : g_a2;
    const __nv_bfloat16* __restrict__ Wg = which ? g_wo2  : g_w2;
    float* __restrict__ Cg = which ? g_y : g_qkv;
    const int ldc = which ? 256 : 768;

    const uint32_t base_a = smem_u32(As);
    const uint32_t base_w = smem_u32(Ws);

    float acc[2][8][4];
    #pragma unroll
    for (int i = 0; i < 2; ++i)
        #pragma unroll
        for (int j = 0; j < 8; ++j)
            #pragma unroll
            for (int q = 0; q < 4; ++q) acc[i][j][q] = 0.f;

    // ldmatrix per-lane base byte offsets (swizzle applied per k-step)
    // A frag (m16k16) for mf: row = wm*32 + mf*16 + (lane&15); kseg16 = (lane>>4)*16
    uint32_t a_row[2], a_k16;
    #pragma unroll
    for (int mf = 0; mf < 2; ++mf) a_row[mf] = (uint32_t)(wm * 32 + mf * 16 + (lane & 15));
    a_k16 = (uint32_t)((lane >> 4) * 16);
    // B frag x4 (two n8 groups) for ng4: n = wn*64 + ng4*16 + (lane>>4)*8 + (lane&7)
    uint32_t b_row[4], b_k16;
    #pragma unroll
    for (int g = 0; g < 4; ++g) b_row[g] = (uint32_t)(wn * 64 + g * 16 + ((lane >> 4) * 8) + (lane & 7));
    b_k16 = (uint32_t)(((lane >> 3) & 1) * 16);

    for (int s = 0; s < 12; ++s) {
        const int seg = s >> 2;
        const int aoff = ((seg == 2) ? 256 : 0) + (s & 3) * 64;
        const int woff = ((seg == 1) ? 256 : 0) + (s & 3) * 64;

        // load tiles: 128 rows x 64 bf16 (128 B/row), 4 x 16B chunks per thread each
        #pragma unroll
        for (int i = 0; i < 4; ++i) {
            int f = i * 256 + tid;
            int row = f >> 3, c16 = f & 7;
            uint32_t so = SWZ128((uint32_t)(row * 128 + c16 * 16));
            *(float4*)((char*)As + so) = *(const float4*)(Ag + ((long)(mBase + row)) * 512 + aoff + c16 * 8);
            *(float4*)((char*)Ws + so) = *(const float4*)(Wg + ((long)(nBase + row)) * 512 + woff + c16 * 8);
        }
        __syncthreads();

        #pragma unroll
        for (int ks = 0; ks < 4; ++ks) {
            const uint32_t kb = (uint32_t)(ks * 32);
            uint32_t a[2][4];
            #pragma unroll
            for (int mf = 0; mf < 2; ++mf) {
                uint32_t off = SWZ128(a_row[mf] * 128 + kb + a_k16);
                ldsm_x4(a[mf][0], a[mf][1], a[mf][2], a[mf][3], base_a + off);
            }
            uint32_t b[4][4];
            #pragma unroll
            for (int g = 0; g < 4; ++g) {
                uint32_t off = SWZ128(b_row[g] * 128 + kb + b_k16);
                ldsm_x4(b[g][0], b[g][1], b[g][2], b[g][3], base_w + off);
            }
            #pragma unroll
            for (int mf = 0; mf < 2; ++mf)
                #pragma unroll
                for (int nf = 0; nf < 8; ++nf) {
                    const uint32_t* bp = b[nf >> 1];
                    if (nf & 1) mma_bf16(acc[mf][nf], a[mf], bp[2], bp[3]);
                    else        mma_bf16(acc[mf][nf], a[mf], bp[0], bp[1]);
                }
        }
        __syncthreads();
    }

    // epilogue: c frag m16n8 -> rows (lane>>2) & +8, cols 2*(lane&3)
    const int colq = (lane & 3) * 2;
    #pragma unroll
    for (int mf = 0; mf < 2; ++mf) {
        int r0 = mBase + wm * 32 + mf * 16 + (lane >> 2);
        #pragma unroll
        for (int nf = 0; nf < 8; ++nf) {
            int col = nBase + wn * 64 + nf * 8 + colq;
            float bx = 0.f, by = 0.f;
            if (!which) { bx = g_bcat[col]; by = g_bcat[col + 1]; }
            float2 v0, v1;
            v0.x = acc[mf][nf][0] + bx; v0.y = acc[mf][nf][1] + by;
            v1.x = acc[mf][nf][2] + bx; v1.y = acc[mf][nf][3] + by;
            *(float2*)(Cg + (long)r0 * ldc + col)       = v0;
            *(float2*)(Cg + (long)(r0 + 8) * ldc + col) = v1;
        }
    }
}

// ---------------- 5) causal flash attention (f32x2, bf16 split output) --------
__global__ void __launch_bounds__(128) attn_kernel() {
    __shared__ float Ks[128][32];
    __shared__ float Vs[128][32];
    const int qc = blockIdx.x, h = blockIdx.y, bn = blockIdx.z;
    const int tid = threadIdx.x;
    const int q = qc * 128 + tid;
    const float scale = 0.17677669529663687f;   // 1/sqrt(32)

    u64 qreg[16];
    {
        const float* qptr = g_qkv + ((long)(bn * S_ + q) * QKVN + h * HD_);
        const u64 sc2 = pack2(scale, scale);
        #pragma unroll
        for (int e = 0; e < 16; ++e)
            qreg[e] = mul2(((const u64*)qptr)[e], sc2);
    }

    float m = -1e30f, l = 0.f;
    u64 acc[16];
    #pragma unroll
    for (int e = 0; e < 16; ++e) acc[e] = 0ULL;

    const int nchunks = qc + 1;
    for (int c = 0; c < nchunks; ++c) {
        #pragma unroll
        for (int r = 0; r < 8; ++r) {
            int f = tid + 128 * r;
            int row = f >> 3, e4 = f & 7;
            const float* base = g_qkv + ((long)(bn * S_ + c * 128 + row) * QKVN + D_ + h * HD_ + e4 * 4);
            *(float4*)&Ks[row][e4 * 4] = *(const float4*)base;
            *(float4*)&Vs[row][e4 * 4] = *(const float4*)(base + D_);
        }
        __syncthreads();

        const int kmax = min(128, q - c * 128 + 1);
        for (int k = 0; k < kmax; ++k) {
            const u64* krow = (const u64*)Ks[k];
            u64 s2[4];
            #pragma unroll
            for (int e = 0; e < 4; ++e) s2[e] = mul2(qreg[e], krow[e]);
            #pragma unroll
            for (int e = 4; e < 16; ++e) s2[e & 3] = fma2(qreg[e], krow[e], s2[e & 3]);
            s2[0] = add2(s2[0], s2[1]);
            s2[2] = add2(s2[2], s2[3]);
            s2[0] = add2(s2[0], s2[2]);
            float slo, shi;
            unpack2(s2[0], slo, shi);
            float s = slo + shi;

            float mn = fmaxf(m, s);
            float p = __expf(s - mn);
            if (mn > m) {
                float corr = __expf(m - mn);
                l *= corr;
                const u64 c2 = pack2(corr, corr);
                #pragma unroll
                for (int e = 0; e < 16; ++e) acc[e] = mul2(acc[e], c2);
                m = mn;
            }
            l += p;
            const u64 p2 = pack2(p, p);
            const u64* vrow = (const u64*)Vs[k];
            #pragma unroll
            for (int e = 0; e < 16; ++e)
                acc[e] = fma2(p2, vrow[e], acc[e]);
        }
        __syncthreads();
    }

    const float inv = 1.f / l;
    __nv_bfloat16* hb = g_att2 + ((long)(bn * S_ + q)) * 512 + h * HD_;
    #pragma unroll
    for (int e = 0; e < 16; ++e) {
        float v0, v1;
        unpack2(acc[e], v0, v1);
        v0 *= inv; v1 *= inv;
        __nv_bfloat16 h0 = __float2bfloat16(v0);
        __nv_bfloat16 h1 = __float2bfloat16(v1);
        __nv_bfloat162 hh; hh.x = h0; hh.y = h1;
        __nv_bfloat162 ll;
        ll.x = __float2bfloat16(v0 - __bfloat162float(h0));
        ll.y = __float2bfloat16(v1 - __bfloat162float(h1));
        ((__nv_bfloat162*)hb)[e] = hh;
        ((__nv_bfloat162*)(hb + 256))[e] = ll;
    }
}

// ---------------- 6) bias + residual + LayerNorm ------------------------------
__global__ void __launch_bounds__(256) ln_kernel(
    const float* __restrict__ x, const float* __restrict__ bo,
    const float* __restrict__ gamma, const float* __restrict__ beta,
    float* __restrict__ out)
{
    const int row = blockIdx.x * 8 + (threadIdx.x >> 5);
    const int lane = threadIdx.x & 31;
    const int bn = row >> 9, s = row & 511;
    const int b = bn >> 3, n = bn & 7;
    const float* yrow = g_y + (long)row * D_;
    const float* xrow = x + (((long)(b * S_ + s)) * N_ + n) * D_;

    float v[8];
    float4 y0 = ((const float4*)yrow)[lane * 2];
    float4 y1 = ((const float4*)yrow)[lane * 2 + 1];
    float4 x0 = ((const float4*)xrow)[lane * 2];
    float4 x1 = ((const float4*)xrow)[lane * 2 + 1];
    float4 b0 = ((const float4*)bo)[lane * 2];
    float4 b1 = ((const float4*)bo)[lane * 2 + 1];
    v[0] = y0.x + x0.x + b0.x; v[1] = y0.y + x0.y + b0.y;
    v[2] = y0.z + x0.z + b0.z; v[3] = y0.w + x0.w + b0.w;
    v[4] = y1.x + x1.x + b1.x; v[5] = y1.y + x1.y + b1.y;
    v[6] = y1.z + x1.z + b1.z; v[7] = y1.w + x1.w + b1.w;

    float sum = 0.f, sq = 0.f;
    #pragma unroll
    for (int j = 0; j < 8; ++j) { sum += v[j]; sq = fmaf(v[j], v[j], sq); }
    #pragma unroll
    for (int o = 16; o > 0; o >>= 1) {
        sum += __shfl_xor_sync(0xFFFFFFFFu, sum, o);
        sq  += __shfl_xor_sync(0xFFFFFFFFu, sq,  o);
    }
    float mu   = sum * (1.f / 256.f);
    float var  = sq * (1.f / 256.f) - mu * mu;
    float rstd = rsqrtf(var + 1e-5f);

    float4 g0 = ((const float4*)gamma)[lane * 2];
    float4 g1 = ((const float4*)gamma)[lane * 2 + 1];
    float4 t0 = ((const float4*)beta)[lane * 2];
    float4 t1 = ((const float4*)beta)[lane * 2 + 1];
    float* orow = out + (((long)(b * S_ + s)) * N_ + n) * D_;
    float4 o1, o2;
    o1.x = (v[0] - mu) * rstd * g0.x + t0.x;
    o1.y = (v[1] - mu) * rstd * g0.y + t0.y;
    o1.z = (v[2] - mu) * rstd * g0.z + t0.z;
    o1.w = (v[3] - mu) * rstd * g0.w + t0.w;
    o2.x = (v[4] - mu) * rstd * g1.x + t1.x;
    o2.y = (v[5] - mu) * rstd * g1.y + t1.y;
    o2.z = (v[6] - mu) * rstd * g1.z + t1.z;
    o2.w = (v[7] - mu) * rstd * g1.w + t1.w;
    ((float4*)orow)[lane * 2]     = o1;
    ((float4*)orow)[lane * 2 + 1] = o2;
}

// ------------------------------ launch ----------------------------------------
// Input order per metadata (dict insertion order in setup_inputs):
//   0:x 1:Wq 2:Wk 3:Wv 4:Wo 5:bq 6:bk 7:bv 8:bo 9:gamma 10:beta 11:num_heads
extern "C" void kernel_launch(void* const* d_in, const int* in_sizes, int n_in,
                              void* d_out, int out_size) {
    const float* x     = (const float*)d_in[0];
    const float* Wq    = (const float*)d_in[1];
    const float* Wk    = (const float*)d_in[2];
    const float* Wv    = (const float*)d_in[3];
    const float* Wo    = (const float*)d_in[4];
    const float* bq    = (const float*)d_in[5];
    const float* bk    = (const float*)d_in[6];
    const float* bv    = (const float*)d_in[7];
    const float* bo    = (const float*)d_in[8];
    const float* gamma = (const float*)d_in[9];
    const float* beta  = (const float*)d_in[10];
    float* out = (float*)d_out;

    pe_kernel<<<256, 256>>>();
    addpe_split_kernel<<<4096, 256>>>(x);
    wsplit_kernel<<<768, 256>>>(Wq, bq, Wk, bk, Wv, bv);
    wosplit_kernel<<<256, 256>>>(Wo);
    mma_gemm_kernel<<<dim3(6, 128), 256>>>(0);          // qkv: N=768
    attn_kernel<<<dim3(4, H_, BN_), 128>>>();
    mma_gemm_kernel<<<dim3(2, 128), 256>>>(1);          // oproj: N=256
    ln_kernel<<<2048, 256>>>(x, bo, gamma, beta, out);
}

// round 7
// speedup vs baseline: 2.8951x; 1.8665x over previous
#include <cuda_runtime.h>
#include <cuda_bf16.h>
#include <math.h>
#include <stdint.h>

// Problem constants (fixed by the dataset)
#define B_   4
#define S_   512
#define N_   8
#define D_   256
#define H_   8
#define HD_  32
#define BN_  (B_ * N_)          // 32
#define T_   (BN_ * S_)         // 16384 rows
#define QKVN 768                // 3*D

// ---------------- warp-mma helpers (baseline PTX, sm_80+) ---------------------
__device__ __forceinline__ uint32_t smem_u32(const void* p) {
    uint32_t a;
    asm("{ .reg .u64 t; cvta.to.shared.u64 t, %1; cvt.u32.u64 %0, t; }" : "=r"(a) : "l"(p));
    return a;
}
__device__ __forceinline__ void ldsm_x4(uint32_t& r0, uint32_t& r1, uint32_t& r2, uint32_t& r3,
                                        uint32_t addr) {
    asm volatile("ldmatrix.sync.aligned.m8n8.x4.shared.b16 {%0,%1,%2,%3}, [%4];"
        : "=r"(r0), "=r"(r1), "=r"(r2), "=r"(r3) : "r"(addr));
}
__device__ __forceinline__ void mma_bf16(float* c, const uint32_t* a, uint32_t b0, uint32_t b1) {
    asm volatile(
        "mma.sync.aligned.m16n8k16.row.col.f32.bf16.bf16.f32 "
        "{%0,%1,%2,%3}, {%4,%5,%6,%7}, {%8,%9}, {%0,%1,%2,%3};"
        : "+f"(c[0]), "+f"(c[1]), "+f"(c[2]), "+f"(c[3])
        : "r"(a[0]), "r"(a[1]), "r"(a[2]), "r"(a[3]), "r"(b0), "r"(b1));
}
// pack two floats as bf16x2: v0 -> low half, v1 -> high half
__device__ __forceinline__ uint32_t bf16x2pack(float v0, float v1) {
    uint32_t r;
    asm("cvt.rn.bf16x2.f32 %0, %1, %2;" : "=r"(r) : "f"(v1), "f"(v0));
    return r;
}
// hi/lo split of a float pair into two bf16x2 regs
__device__ __forceinline__ void split2(float v0, float v1, uint32_t& hi, uint32_t& lo) {
    hi = bf16x2pack(v0, v1);
    float h0 = __uint_as_float(hi << 16);
    float h1 = __uint_as_float(hi & 0xFFFF0000u);
    lo = bf16x2pack(v0 - h0, v1 - h1);
}
#define SWZ128(off) ((off) ^ (((off) >> 3) & 0x70))

// ---------------- scratch (device globals; no runtime allocation) -------------
__device__ float g_pe[S_ * D_];                        // 0.5 MB
__device__ __nv_bfloat16 g_a2[(long)T_ * 512];         // 16 MB  [hi(256)|lo(256)] per row
__device__ __nv_bfloat16 g_w2[QKVN * 512];             // 0.75 MB [Whi|Wlo] rows q,k,v
__device__ __nv_bfloat16 g_wo2[D_ * 512];              // 0.25 MB
__device__ float g_bcat[QKVN];
// attention inputs, written by qkv GEMM epilogue:
__device__ __nv_bfloat16 g_qh[(long)BN_ * H_ * S_ * HD_];   // [bnh][s][e] Q*scale hi
__device__ __nv_bfloat16 g_ql[(long)BN_ * H_ * S_ * HD_];
__device__ __nv_bfloat16 g_kh[(long)BN_ * H_ * S_ * HD_];
__device__ __nv_bfloat16 g_kl[(long)BN_ * H_ * S_ * HD_];
__device__ __nv_bfloat16 g_vth[(long)BN_ * H_ * HD_ * S_];  // [bnh][e][s]  V transposed
__device__ __nv_bfloat16 g_vtl[(long)BN_ * H_ * HD_ * S_];
__device__ __nv_bfloat16 g_att2[(long)T_ * 512];       // 16 MB attention out hi/lo
__device__ float g_y[(long)T_ * D_];                   // 16 MB out-proj result

// ---------------- 1) positional encoding table -------------------------------
__global__ void pe_kernel() {
    int idx = blockIdx.x * 256 + threadIdx.x;       // 65536 = S * D/2
    int s = idx >> 7;
    int i = idx & 127;
    float div = expf((float)(2 * i) * (-0.035977892078031970f)); // -ln(10000)/256
    float sn, cs;
    sincosf((float)s * div, &sn, &cs);
    g_pe[s * D_ + 2 * i]     = sn;
    g_pe[s * D_ + 2 * i + 1] = cs;
}

// ---------------- 2) x + pe -> bf16 hi/lo split, (B,S,N,D)->(BN,S,D) ----------
__global__ void addpe_split_kernel(const float* __restrict__ x) {
    int idx = blockIdx.x * 256 + threadIdx.x;       // 1,048,576 groups of 4
    int d4 = idx & 63;
    int s  = (idx >> 6) & 511;
    int bn = idx >> 15;
    int b = bn >> 3, n = bn & 7;
    const float4 xv = *(const float4*)(x + ((((long)b * S_ + s) * N_ + n) * D_ + d4 * 4));
    const float4 pv = *(const float4*)(g_pe + (s * D_ + d4 * 4));
    float v[4] = {xv.x + pv.x, xv.y + pv.y, xv.z + pv.z, xv.w + pv.w};
    long t = (long)bn * S_ + s;
    __nv_bfloat16* hb = g_a2 + t * 512 + d4 * 4;
    uint32_t h01, l01, h23, l23;
    split2(v[0], v[1], h01, l01);
    split2(v[2], v[3], h23, l23);
    ((uint32_t*)hb)[0] = h01;
    ((uint32_t*)hb)[1] = h23;
    ((uint32_t*)(hb + 256))[0] = l01;
    ((uint32_t*)(hb + 256))[1] = l23;
}

// ---------------- 3) weight concat + hi/lo split ------------------------------
__global__ void wsplit_kernel(const float* __restrict__ Wq, const float* __restrict__ bq,
                              const float* __restrict__ Wk, const float* __restrict__ bk,
                              const float* __restrict__ Wv, const float* __restrict__ bv) {
    int idx = blockIdx.x * 256 + threadIdx.x;       // 196608
    int j = idx >> 8, k = idx & 255;
    const float* src; const float* bsrc;
    int jj = j & 255;
    if (j < 256)      { src = Wq; bsrc = bq; }
    else if (j < 512) { src = Wk; bsrc = bk; }
    else              { src = Wv; bsrc = bv; }
    float v = src[jj * D_ + k];
    __nv_bfloat16 h = __float2bfloat16(v);
    g_w2[j * 512 + k]       = h;
    g_w2[j * 512 + 256 + k] = __float2bfloat16(v - __bfloat162float(h));
    if (k == 0) g_bcat[j] = bsrc[jj];
}

__global__ void wosplit_kernel(const float* __restrict__ Wo) {
    int idx = blockIdx.x * 256 + threadIdx.x;       // 65536
    int j = idx >> 8, k = idx & 255;
    float v = Wo[j * D_ + k];
    __nv_bfloat16 h = __float2bfloat16(v);
    g_wo2[j * 512 + k]       = h;
    g_wo2[j * 512 + 256 + k] = __float2bfloat16(v - __bfloat162float(h));
}

// ---------------- 4) warp-mma GEMM (3-term bf16 split) ------------------------
// which=0: qkv — epilogue writes split bf16 Q(scaled)/K and transposed V
// which=1: oproj — writes fp32 to g_y
__global__ void __launch_bounds__(256) mma_gemm_kernel(int which) {
    __shared__ __align__(1024) __nv_bfloat16 As[128 * 64];  // 16 KB
    __shared__ __align__(1024) __nv_bfloat16 Ws[128 * 64];  // 16 KB
    const int tid = threadIdx.x;
    const int wid = tid >> 5, lane = tid & 31;
    const int wm = wid & 3;          // 4 warps along M (32 rows each)
    const int wn = wid >> 2;         // 2 warps along N (64 cols each)
    const int mBase = blockIdx.y * 128;
    const int nBase = blockIdx.x * 128;

    const __nv_bfloat16* __restrict__ Ag = which ? g_att2 : g_a2;
    const __nv_bfloat16* __restrict__ Wg = which ? g_wo2  : g_w2;

    const uint32_t base_a = smem_u32(As);
    const uint32_t base_w = smem_u32(Ws);

    float acc[2][8][4];
    #pragma unroll
    for (int i = 0; i < 2; ++i)
        #pragma unroll
        for (int j = 0; j < 8; ++j)
            #pragma unroll
            for (int q = 0; q < 4; ++q) acc[i][j][q] = 0.f;

    uint32_t a_row[2], a_k16;
    #pragma unroll
    for (int mf = 0; mf < 2; ++mf) a_row[mf] = (uint32_t)(wm * 32 + mf * 16 + (lane & 15));
    a_k16 = (uint32_t)((lane >> 4) * 16);
    uint32_t b_row[4], b_k16;
    #pragma unroll
    for (int g = 0; g < 4; ++g) b_row[g] = (uint32_t)(wn * 64 + g * 16 + ((lane >> 4) * 8) + (lane & 7));
    b_k16 = (uint32_t)(((lane >> 3) & 1) * 16);

    for (int s = 0; s < 12; ++s) {
        const int seg = s >> 2;
        const int aoff = ((seg == 2) ? 256 : 0) + (s & 3) * 64;
        const int woff = ((seg == 1) ? 256 : 0) + (s & 3) * 64;

        #pragma unroll
        for (int i = 0; i < 4; ++i) {
            int f = i * 256 + tid;
            int row = f >> 3, c16 = f & 7;
            uint32_t so = SWZ128((uint32_t)(row * 128 + c16 * 16));
            *(float4*)((char*)As + so) = *(const float4*)(Ag + ((long)(mBase + row)) * 512 + aoff + c16 * 8);
            *(float4*)((char*)Ws + so) = *(const float4*)(Wg + ((long)(nBase + row)) * 512 + woff + c16 * 8);
        }
        __syncthreads();

        #pragma unroll
        for (int ks = 0; ks < 4; ++ks) {
            const uint32_t kb = (uint32_t)(ks * 32);
            uint32_t a[2][4];
            #pragma unroll
            for (int mf = 0; mf < 2; ++mf) {
                uint32_t off = SWZ128(a_row[mf] * 128 + kb + a_k16);
                ldsm_x4(a[mf][0], a[mf][1], a[mf][2], a[mf][3], base_a + off);
            }
            uint32_t b[4][4];
            #pragma unroll
            for (int g = 0; g < 4; ++g) {
                uint32_t off = SWZ128(b_row[g] * 128 + kb + b_k16);
                ldsm_x4(b[g][0], b[g][1], b[g][2], b[g][3], base_w + off);
            }
            #pragma unroll
            for (int mf = 0; mf < 2; ++mf)
                #pragma unroll
                for (int nf = 0; nf < 8; ++nf) {
                    const uint32_t* bp = b[nf >> 1];
                    if (nf & 1) mma_bf16(acc[mf][nf], a[mf], bp[2], bp[3]);
                    else        mma_bf16(acc[mf][nf], a[mf], bp[0], bp[1]);
                }
        }
        __syncthreads();
    }

    const int colq = (lane & 3) * 2;
    const float qscale = 0.17677669529663687f;   // 1/sqrt(32)
    #pragma unroll
    for (int mf = 0; mf < 2; ++mf) {
        int r0 = mBase + wm * 32 + mf * 16 + (lane >> 2);
        #pragma unroll
        for (int nf = 0; nf < 8; ++nf) {
            int col = nBase + wn * 64 + nf * 8 + colq;
            if (which) {
                float2 v0, v1;
                v0.x = acc[mf][nf][0]; v0.y = acc[mf][nf][1];
                v1.x = acc[mf][nf][2]; v1.y = acc[mf][nf][3];
                *(float2*)(g_y + (long)r0 * D_ + col)       = v0;
                *(float2*)(g_y + (long)(r0 + 8) * D_ + col) = v1;
            } else {
                float bx = g_bcat[col], by = g_bcat[col + 1];
                float v00 = acc[mf][nf][0] + bx, v01 = acc[mf][nf][1] + by;   // row r0
                float v10 = acc[mf][nf][2] + bx, v11 = acc[mf][nf][3] + by;   // row r0+8
                int type = col >> 8, d = col & 255, hh = d >> 5, e = d & 31;
                if (type == 0) { v00 *= qscale; v01 *= qscale; v10 *= qscale; v11 *= qscale; }
                uint32_t h01, l01, h23, l23;
                split2(v00, v01, h01, l01);
                split2(v10, v11, h23, l23);
                int bnh0 = ((r0 >> 9) * H_ + hh);
                int s0 = r0 & 511;
                if (type < 2) {
                    __nv_bfloat16* dh = type ? g_kh : g_qh;
                    __nv_bfloat16* dl = type ? g_kl : g_ql;
                    long a0 = ((long)bnh0 * S_ + s0) * HD_ + e;
                    *(uint32_t*)(dh + a0)            = h01;
                    *(uint32_t*)(dl + a0)            = l01;
                    *(uint32_t*)(dh + a0 + 8 * HD_)  = h23;
                    *(uint32_t*)(dl + a0 + 8 * HD_)  = l23;
                } else {
                    // V transposed: [bnh][e][s]
                    long vb = ((long)bnh0 * HD_ + e) * S_ + s0;
                    unsigned short* vh = (unsigned short*)g_vth;
                    unsigned short* vl = (unsigned short*)g_vtl;
                    vh[vb]           = (unsigned short)(h01 & 0xFFFF);
                    vh[vb + S_]      = (unsigned short)(h01 >> 16);
                    vh[vb + 8]       = (unsigned short)(h23 & 0xFFFF);
                    vh[vb + S_ + 8]  = (unsigned short)(h23 >> 16);
                    vl[vb]           = (unsigned short)(l01 & 0xFFFF);
                    vl[vb + S_]      = (unsigned short)(l01 >> 16);
                    vl[vb + 8]       = (unsigned short)(l23 & 0xFFFF);
                    vl[vb + S_ + 8]  = (unsigned short)(l23 >> 16);
                }
            }
        }
    }
}

// ---------------- 5) causal flash attention (tensor cores, bf16 split) --------
// grid (4 q-tiles of 128, 8 heads, 32 bn); 8 warps; warp = 16 query rows.
__global__ void __launch_bounds__(256) attn_mma_kernel() {
    __shared__ __align__(128)  __nv_bfloat16 sQh[128 * 40];   // stride 40 bf16 = 80B
    __shared__ __align__(128)  __nv_bfloat16 sQl[128 * 40];
    __shared__ __align__(128)  __nv_bfloat16 sKh[64 * 40];
    __shared__ __align__(128)  __nv_bfloat16 sKl[64 * 40];
    __shared__ __align__(1024) __nv_bfloat16 sVh[32 * 64];    // V^T tile, SW128
    __shared__ __align__(1024) __nv_bfloat16 sVl[32 * 64];
    const int tid = threadIdx.x, wid = tid >> 5, lane = tid & 31;
    const int qBase = blockIdx.x * 128;
    const int h = blockIdx.y, bn = blockIdx.z;
    const int bnh = bn * H_ + h;
    const int qw = qBase + wid * 16;
    const long kvoff = (long)bnh * S_ * HD_;
    const __nv_bfloat16* qhg = g_qh + kvoff;
    const __nv_bfloat16* qlg = g_ql + kvoff;
    const __nv_bfloat16* khg = g_kh + kvoff;
    const __nv_bfloat16* klg = g_kl + kvoff;
    const __nv_bfloat16* vhg = g_vth + kvoff;   // [32][512]
    const __nv_bfloat16* vlg = g_vtl + kvoff;

    // load Q tile (rows qBase..qBase+127, 32 dims) into smem
    #pragma unroll
    for (int i = 0; i < 2; ++i) {
        int f = i * 256 + tid, row = f >> 2, c = f & 3;
        *(float4*)((char*)sQh + row * 80 + c * 16) = *(const float4*)(qhg + (long)(qBase + row) * 32 + c * 8);
        *(float4*)((char*)sQl + row * 80 + c * 16) = *(const float4*)(qlg + (long)(qBase + row) * 32 + c * 8);
    }
    __syncthreads();

    const uint32_t bQh = smem_u32(sQh), bQl = smem_u32(sQl);
    const uint32_t bKh = smem_u32(sKh), bKl = smem_u32(sKl);
    const uint32_t bVh = smem_u32(sVh), bVl = smem_u32(sVl);

    uint32_t qfh[2][4], qfl[2][4];
    #pragma unroll
    for (int ks = 0; ks < 2; ++ks) {
        uint32_t off = (uint32_t)((wid * 16 + (lane & 15)) * 80 + ks * 32 + (lane >> 4) * 16);
        ldsm_x4(qfh[ks][0], qfh[ks][1], qfh[ks][2], qfh[ks][3], bQh + off);
        ldsm_x4(qfl[ks][0], qfl[ks][1], qfl[ks][2], qfl[ks][3], bQl + off);
    }

    float o[4][4];
    #pragma unroll
    for (int i = 0; i < 4; ++i)
        #pragma unroll
        for (int j = 0; j < 4; ++j) o[i][j] = 0.f;
    float m0 = -1e30f, m1 = -1e30f, l0 = 0.f, l1 = 0.f;

    const int nkt_w = (qw >> 6) + 1;          // tiles this warp computes
    const int nkt_b = (qBase >> 6) + 2;       // tiles the block loads

    for (int kt = 0; kt < nkt_b; ++kt) {
        {   // load K tile (64x32, stride 40) and V^T tile (32x64, SW128)
            int row = tid >> 2, c = tid & 3;
            *(float4*)((char*)sKh + row * 80 + c * 16) = *(const float4*)(khg + (long)(kt * 64 + row) * 32 + c * 8);
            *(float4*)((char*)sKl + row * 80 + c * 16) = *(const float4*)(klg + (long)(kt * 64 + row) * 32 + c * 8);
            int vr = tid >> 3, vc = tid & 7;
            uint32_t so = SWZ128((uint32_t)(vr * 128 + vc * 16));
            *(float4*)((char*)sVh + so) = *(const float4*)(vhg + (long)vr * S_ + kt * 64 + vc * 8);
            *(float4*)((char*)sVl + so) = *(const float4*)(vlg + (long)vr * S_ + kt * 64 + vc * 8);
        }
        __syncthreads();

        if (kt < nkt_w) {
            float s[8][4];
            #pragma unroll
            for (int nt = 0; nt < 8; ++nt)
                #pragma unroll
                for (int j = 0; j < 4; ++j) s[nt][j] = 0.f;

            #pragma unroll
            for (int ks = 0; ks < 2; ++ks) {
                uint32_t bh[4][4], bl[4][4];
                #pragma unroll
                for (int g = 0; g < 4; ++g) {
                    uint32_t off = (uint32_t)((g * 16 + (lane >> 4) * 8 + (lane & 7)) * 80
                                              + ks * 32 + ((lane >> 3) & 1) * 16);
                    ldsm_x4(bh[g][0], bh[g][1], bh[g][2], bh[g][3], bKh + off);
                    ldsm_x4(bl[g][0], bl[g][1], bl[g][2], bl[g][3], bKl + off);
                }
                #pragma unroll
                for (int nt = 0; nt < 8; ++nt) {
                    const uint32_t* ph = bh[nt >> 1];
                    const uint32_t* pl = bl[nt >> 1];
                    int e0 = (nt & 1) * 2, e1 = e0 + 1;
                    mma_bf16(s[nt], qfh[ks], ph[e0], ph[e1]);
                    mma_bf16(s[nt], qfh[ks], pl[e0], pl[e1]);
                    mma_bf16(s[nt], qfl[ks], ph[e0], ph[e1]);
                }
            }

            // causal mask on the diagonal tile
            if (kt == (qw >> 6)) {
                int q0 = qw + (lane >> 2), q1 = q0 + 8;
                #pragma unroll
                for (int nt = 0; nt < 8; ++nt) {
                    int k0 = kt * 64 + nt * 8 + ((lane & 3) << 1);
                    if (k0 > q0)     s[nt][0] = -1e9f;
                    if (k0 + 1 > q0) s[nt][1] = -1e9f;
                    if (k0 > q1)     s[nt][2] = -1e9f;
                    if (k0 + 1 > q1) s[nt][3] = -1e9f;
                }
            }

            // online softmax
            float mx0 = -1e30f, mx1 = -1e30f;
            #pragma unroll
            for (int nt = 0; nt < 8; ++nt) {
                mx0 = fmaxf(mx0, fmaxf(s[nt][0], s[nt][1]));
                mx1 = fmaxf(mx1, fmaxf(s[nt][2], s[nt][3]));
            }
            mx0 = fmaxf(mx0, __shfl_xor_sync(0xFFFFFFFFu, mx0, 1));
            mx0 = fmaxf(mx0, __shfl_xor_sync(0xFFFFFFFFu, mx0, 2));
            mx1 = fmaxf(mx1, __shfl_xor_sync(0xFFFFFFFFu, mx1, 1));
            mx1 = fmaxf(mx1, __shfl_xor_sync(0xFFFFFFFFu, mx1, 2));
            float nm0 = fmaxf(m0, mx0), nm1 = fmaxf(m1, mx1);
            float a0 = __expf(m0 - nm0), a1 = __expf(m1 - nm1);
            m0 = nm0; m1 = nm1;

            float sum0 = 0.f, sum1 = 0.f;
            uint32_t aph[4][4], apl[4][4];
            #pragma unroll
            for (int nt = 0; nt < 8; ++nt) {
                float p0 = __expf(s[nt][0] - m0), p1 = __expf(s[nt][1] - m0);
                float p2 = __expf(s[nt][2] - m1), p3 = __expf(s[nt][3] - m1);
                sum0 += p0 + p1; sum1 += p2 + p3;
                uint32_t h01, l01, h23, l23;
                split2(p0, p1, h01, l01);
                split2(p2, p3, h23, l23);
                int kk = nt >> 1, r = (nt & 1) * 2;
                aph[kk][r]     = h01;   // (rows0-7, k lo half of this 16-key group)
                aph[kk][r + 1] = h23;   // (rows8-15)
                apl[kk][r]     = l01;
                apl[kk][r + 1] = l23;
            }
            sum0 += __shfl_xor_sync(0xFFFFFFFFu, sum0, 1);
            sum0 += __shfl_xor_sync(0xFFFFFFFFu, sum0, 2);
            sum1 += __shfl_xor_sync(0xFFFFFFFFu, sum1, 1);
            sum1 += __shfl_xor_sync(0xFFFFFFFFu, sum1, 2);
            l0 = l0 * a0 + sum0;
            l1 = l1 * a1 + sum1;
            #pragma unroll
            for (int nt = 0; nt < 4; ++nt) {
                o[nt][0] *= a0; o[nt][1] *= a0;
                o[nt][2] *= a1; o[nt][3] *= a1;
            }

            // P @ V  (V^T tile: rows = hd, cols = keys; same frag map as GEMM B)
            #pragma unroll
            for (int kk = 0; kk < 4; ++kk) {
                uint32_t vh[2][4], vl[2][4];
                #pragma unroll
                for (int g = 0; g < 2; ++g) {
                    uint32_t off = SWZ128((uint32_t)((g * 16 + (lane >> 4) * 8 + (lane & 7)) * 128
                                                     + kk * 32 + ((lane >> 3) & 1) * 16));
                    ldsm_x4(vh[g][0], vh[g][1], vh[g][2], vh[g][3], bVh + off);
                    ldsm_x4(vl[g][0], vl[g][1], vl[g][2], vl[g][3], bVl + off);
                }
                #pragma unroll
                for (int nt = 0; nt < 4; ++nt) {
                    const uint32_t* ph = vh[nt >> 1];
                    const uint32_t* pl = vl[nt >> 1];
                    int e0 = (nt & 1) * 2, e1 = e0 + 1;
                    mma_bf16(o[nt], aph[kk], ph[e0], ph[e1]);
                    mma_bf16(o[nt], aph[kk], pl[e0], pl[e1]);
                    mma_bf16(o[nt], apl[kk], ph[e0], ph[e1]);
                }
            }
        }
        __syncthreads();
    }

    // epilogue: normalize, split, write g_att2
    float i0 = 1.f / l0, i1 = 1.f / l1;
    long t0 = (long)bn * S_ + qw + (lane >> 2);
    #pragma unroll
    for (int nt = 0; nt < 4; ++nt) {
        int col = h * 32 + nt * 8 + ((lane & 3) << 1);
        float v00 = o[nt][0] * i0, v01 = o[nt][1] * i0;
        float v10 = o[nt][2] * i1, v11 = o[nt][3] * i1;
        uint32_t h01, l01, h23, l23;
        split2(v00, v01, h01, l01);
        split2(v10, v11, h23, l23);
        *(uint32_t*)(g_att2 + t0 * 512 + col)             = h01;
        *(uint32_t*)(g_att2 + t0 * 512 + 256 + col)       = l01;
        *(uint32_t*)(g_att2 + (t0 + 8) * 512 + col)       = h23;
        *(uint32_t*)(g_att2 + (t0 + 8) * 512 + 256 + col) = l23;
    }
}

// ---------------- 6) bias + residual + LayerNorm ------------------------------
__global__ void __launch_bounds__(256) ln_kernel(
    const float* __restrict__ x, const float* __restrict__ bo,
    const float* __restrict__ gamma, const float* __restrict__ beta,
    float* __restrict__ out)
{
    const int row = blockIdx.x * 8 + (threadIdx.x >> 5);
    const int lane = threadIdx.x & 31;
    const int bn = row >> 9, s = row & 511;
    const int b = bn >> 3, n = bn & 7;
    const float* yrow = g_y + (long)row * D_;
    const float* xrow = x + (((long)(b * S_ + s)) * N_ + n) * D_;

    float v[8];
    float4 y0 = ((const float4*)yrow)[lane * 2];
    float4 y1 = ((const float4*)yrow)[lane * 2 + 1];
    float4 x0 = ((const float4*)xrow)[lane * 2];
    float4 x1 = ((const float4*)xrow)[lane * 2 + 1];
    float4 b0 = ((const float4*)bo)[lane * 2];
    float4 b1 = ((const float4*)bo)[lane * 2 + 1];
    v[0] = y0.x + x0.x + b0.x; v[1] = y0.y + x0.y + b0.y;
    v[2] = y0.z + x0.z + b0.z; v[3] = y0.w + x0.w + b0.w;
    v[4] = y1.x + x1.x + b1.x; v[5] = y1.y + x1.y + b1.y;
    v[6] = y1.z + x1.z + b1.z; v[7] = y1.w + x1.w + b1.w;

    float sum = 0.f, sq = 0.f;
    #pragma unroll
    for (int j = 0; j < 8; ++j) { sum += v[j]; sq = fmaf(v[j], v[j], sq); }
    #pragma unroll
    for (int o = 16; o > 0; o >>= 1) {
        sum += __shfl_xor_sync(0xFFFFFFFFu, sum, o);
        sq  += __shfl_xor_sync(0xFFFFFFFFu, sq,  o);
    }
    float mu   = sum * (1.f / 256.f);
    float var  = sq * (1.f / 256.f) - mu * mu;
    float rstd = rsqrtf(var + 1e-5f);

    float4 g0 = ((const float4*)gamma)[lane * 2];
    float4 g1 = ((const float4*)gamma)[lane * 2 + 1];
    float4 t0 = ((const float4*)beta)[lane * 2];
    float4 t1 = ((const float4*)beta)[lane * 2 + 1];
    float* orow = out + (((long)(b * S_ + s)) * N_ + n) * D_;
    float4 o1, o2;
    o1.x = (v[0] - mu) * rstd * g0.x + t0.x;
    o1.y = (v[1] - mu) * rstd * g0.y + t0.y;
    o1.z = (v[2] - mu) * rstd * g0.z + t0.z;
    o1.w = (v[3] - mu) * rstd * g0.w + t0.w;
    o2.x = (v[4] - mu) * rstd * g1.x + t1.x;
    o2.y = (v[5] - mu) * rstd * g1.y + t1.y;
    o2.z = (v[6] - mu) * rstd * g1.z + t1.z;
    o2.w = (v[7] - mu) * rstd * g1.w + t1.w;
    ((float4*)orow)[lane * 2]     = o1;
    ((float4*)orow)[lane * 2 + 1] = o2;
}

// ------------------------------ launch ----------------------------------------
// Input order per metadata (dict insertion order in setup_inputs):
//   0:x 1:Wq 2:Wk 3:Wv 4:Wo 5:bq 6:bk 7:bv 8:bo 9:gamma 10:beta 11:num_heads
extern "C" void kernel_launch(void* const* d_in, const int* in_sizes, int n_in,
                              void* d_out, int out_size) {
    const float* x     = (const float*)d_in[0];
    const float* Wq    = (const float*)d_in[1];
    const float* Wk    = (const float*)d_in[2];
    const float* Wv    = (const float*)d_in[3];
    const float* Wo    = (const float*)d_in[4];
    const float* bq    = (const float*)d_in[5];
    const float* bk    = (const float*)d_in[6];
    const float* bv    = (const float*)d_in[7];
    const float* bo    = (const float*)d_in[8];
    const float* gamma = (const float*)d_in[9];
    const float* beta  = (const float*)d_in[10];
    float* out = (float*)d_out;

    pe_kernel<<<256, 256>>>();
    addpe_split_kernel<<<4096, 256>>>(x);
    wsplit_kernel<<<768, 256>>>(Wq, bq, Wk, bk, Wv, bv);
    wosplit_kernel<<<256, 256>>>(Wo);
    mma_gemm_kernel<<<dim3(6, 128), 256>>>(0);          // qkv: N=768 -> split Q/K/V^T
    attn_mma_kernel<<<dim3(4, H_, BN_), 256>>>();
    mma_gemm_kernel<<<dim3(2, 128), 256>>>(1);          // oproj: N=256 -> g_y
    ln_kernel<<<2048, 256>>>(x, bo, gamma, beta, out);
}